// round 6
// baseline (speedup 1.0000x reference)
#include <cuda_runtime.h>
#include <math.h>

// GJR-GARCH(1,1):  h[t] = c[t] + beta*h[t-1],  h[0]=var(returns,ddof=1)
// c[t] = omega + (alpha + gamma*[r[t-1]<0]) * r[t-1]^2
// Output: [sqrt(h) | h], each N floats.
//
// Warp owns 2048 elems = 16 rounds of 128 (lane owns a float4), 4-way ILP
// groups; cross-round dependence is one fma (beta^128 carry). B-only warp
// scan with uniform step multipliers m^d (m=beta^4). 128-term window carry.
// R6: __launch_bounds__(256,5) for 5 blocks/SM occupancy + __stcs streaming
// stores (output never re-read; keep L2 for the input stream).

#define WPB   8
#define TPB   (WPB * 32)        // 256
#define CHUNK 2048
#define BLK   (WPB * CHUNK)     // 16384 elements per block
#define NPART_MAX 32768
#define FULLMASK 0xffffffffu

__device__ float    g_ps[NPART_MAX];
__device__ float    g_pq[NPART_MAX];
__device__ unsigned g_done = 0;

__device__ __forceinline__ float sqrt_approx(float x) {
    float y; asm("sqrt.approx.f32 %0, %1;" : "=f"(y) : "f"(x)); return y;
}

// exact m^e for 0<=e<=31 from precomputed squarings
__device__ __forceinline__ float powk(float m1, float m2, float m4,
                                      float m8, float m16, int e) {
    float p = 1.f;
    if (e & 1)  p *= m1;
    if (e & 2)  p *= m2;
    if (e & 4)  p *= m4;
    if (e & 8)  p *= m8;
    if (e & 16) p *= m16;
    return p;
}

__global__ void __launch_bounds__(TPB, 5) k_all(
    const float* __restrict__ r,
    const float* __restrict__ p_omega, const float* __restrict__ p_alpha,
    const float* __restrict__ p_beta,  const float* __restrict__ p_gamma,
    float* __restrict__ out, int n)
{
    const int tid  = threadIdx.x;
    const int w    = tid >> 5;
    const int lane = tid & 31;
    const int base = blockIdx.x * BLK + w * CHUNK;

    const float omega = __ldg(p_omega);
    const float alpha = __ldg(p_alpha);
    const float beta  = __ldg(p_beta);
    const float gamma = __ldg(p_gamma);
    const float ag = alpha + gamma;

    // powers of beta with power-of-two exponents (exact squarings)
    const float bp1 = beta;
    const float bp2 = bp1 * bp1, bp4 = bp2 * bp2, bp8 = bp4 * bp4;
    const float bp16 = bp8 * bp8, bp32 = bp16 * bp16;
    const float bp64 = bp32 * bp32, bp128 = bp64 * bp64;
    const float b3 = bp1 * bp2;

    // per-lane constant: beta^(4*lane)
    const float bl4 = powk(bp4, bp8, bp16, bp32, bp64, lane);

    float s = 0.f, q = 0.f;

    if (base < n) {
        // ---- chunk carry-in Hc ~= h[base-1]: 128-term window (coalesced) ----
        float Hc = 0.f;
        if (base > 0) {
            float bj = powk(bp1, bp2, bp4, bp8, bp16, lane);   // beta^lane
            float P  = 0.f;
            const float* rb = r + base - 2 - lane;       // term j = 32*i + lane
            #pragma unroll
            for (int i = 0; i < 4; i++) {
                float rp   = rb[-32 * i];
                float coef = (rp < 0.f) ? ag : alpha;
                P  = fmaf(bj, fmaf(coef * rp, rp, omega), P);
                bj *= bp32;
            }
            #pragma unroll
            for (int d = 16; d; d >>= 1) P += __shfl_xor_sync(FULLMASK, P, d);
            Hc = P;
        }
        float rlast = (base > 0) ? __ldg(r + base - 1) : 0.f;

        if (base + CHUNK <= n && ((n & 3) == 0)) {
            // =============== fast path: 4 groups x 4 ILP rounds ===============
            const float4* r4  = (const float4*)(r + base);
            float4*       oh4 = (float4*)(out + n + base);
            float4*       os4 = (float4*)(out + base);

            #pragma unroll
            for (int g = 0; g < 4; g++) {
                float4 v[4];
                #pragma unroll
                for (int i = 0; i < 4; i++) v[i] = r4[(4 * g + i) * 32 + lane];

                // c-transform + local affine prefix; variance fused; rp0 inline
                float p0[4], p1[4], p2[4], p3[4];
                float rl_next = rlast;
                #pragma unroll
                for (int i = 0; i < 4; i++) {
                    s += (v[i].x + v[i].y) + (v[i].z + v[i].w);
                    q = fmaf(v[i].x, v[i].x, q); q = fmaf(v[i].y, v[i].y, q);
                    q = fmaf(v[i].z, v[i].z, q); q = fmaf(v[i].w, v[i].w, q);

                    float su  = __shfl_up_sync(FULLMASK, v[i].w, 1);
                    float t31 = __shfl_sync(FULLMASK, v[i].w, 31);
                    float rp0 = (lane == 0) ? rl_next : su;
                    rl_next = t31;

                    float c0, c1, c2, c3;
                    { float t = rp0;    float cf = (t < 0.f) ? ag : alpha; c0 = fmaf(cf * t, t, omega); }
                    { float t = v[i].x; float cf = (t < 0.f) ? ag : alpha; c1 = fmaf(cf * t, t, omega); }
                    { float t = v[i].y; float cf = (t < 0.f) ? ag : alpha; c2 = fmaf(cf * t, t, omega); }
                    { float t = v[i].z; float cf = (t < 0.f) ? ag : alpha; c3 = fmaf(cf * t, t, omega); }
                    p0[i] = c0;
                    p1[i] = fmaf(bp1, c0, c1);
                    p2[i] = fmaf(bp1, p1[i], c2);
                    p3[i] = fmaf(bp1, p2[i], c3);
                }
                rlast = rl_next;

                // 4 interleaved B-only warp scans; step d multiplier = (beta^4)^d
                float B[4];
                #pragma unroll
                for (int i = 0; i < 4; i++) B[i] = p3[i];
                {
                    float Bp[4];
                    #pragma unroll
                    for (int i = 0; i < 4; i++) Bp[i] = __shfl_up_sync(FULLMASK, B[i], 1);
                    #pragma unroll
                    for (int i = 0; i < 4; i++) if (lane >= 1) B[i] = fmaf(bp4, Bp[i], B[i]);
                    #pragma unroll
                    for (int i = 0; i < 4; i++) Bp[i] = __shfl_up_sync(FULLMASK, B[i], 2);
                    #pragma unroll
                    for (int i = 0; i < 4; i++) if (lane >= 2) B[i] = fmaf(bp8, Bp[i], B[i]);
                    #pragma unroll
                    for (int i = 0; i < 4; i++) Bp[i] = __shfl_up_sync(FULLMASK, B[i], 4);
                    #pragma unroll
                    for (int i = 0; i < 4; i++) if (lane >= 4) B[i] = fmaf(bp16, Bp[i], B[i]);
                    #pragma unroll
                    for (int i = 0; i < 4; i++) Bp[i] = __shfl_up_sync(FULLMASK, B[i], 8);
                    #pragma unroll
                    for (int i = 0; i < 4; i++) if (lane >= 8) B[i] = fmaf(bp32, Bp[i], B[i]);
                    #pragma unroll
                    for (int i = 0; i < 4; i++) Bp[i] = __shfl_up_sync(FULLMASK, B[i], 16);
                    #pragma unroll
                    for (int i = 0; i < 4; i++) if (lane >= 16) B[i] = fmaf(bp64, Bp[i], B[i]);
                }

                // exclusive value + totals, carry chain (one fma per round)
                float Bx[4], T[4];
                #pragma unroll
                for (int i = 0; i < 4; i++) {
                    float bu = __shfl_up_sync(FULLMASK, B[i], 1);
                    Bx[i] = (lane == 0) ? 0.f : bu;
                    T[i]  = __shfl_sync(FULLMASK, B[i], 31);
                }
                float Hin[4];
                Hin[0] = Hc;
                Hin[1] = fmaf(bp128, Hin[0], T[0]);
                Hin[2] = fmaf(bp128, Hin[1], T[1]);
                Hin[3] = fmaf(bp128, Hin[2], T[2]);
                Hc     = fmaf(bp128, Hin[3], T[3]);

                // apply carries + streaming stores
                #pragma unroll
                for (int i = 0; i < 4; i++) {
                    float Hl = fmaf(bl4, Hin[i], Bx[i]);   // h[a-1] for this lane
                    float h0v = fmaf(bp1, Hl, p0[i]);
                    float h1v = fmaf(bp2, Hl, p1[i]);
                    float h2v = fmaf(b3,  Hl, p2[i]);
                    float h3v = fmaf(bp4, Hl, p3[i]);
                    __stcs(&oh4[(4 * g + i) * 32 + lane],
                           make_float4(h0v, h1v, h2v, h3v));
                    __stcs(&os4[(4 * g + i) * 32 + lane],
                           make_float4(sqrt_approx(h0v), sqrt_approx(h1v),
                                       sqrt_approx(h2v), sqrt_approx(h3v)));
                }
            }
        } else {
            // =============== guarded scalar path (partial chunk) ===============
            #pragma unroll 1
            for (int j = 0; j < CHUNK / 128; j++) {
                int e0 = base + j * 128 + 4 * lane;
                float x0 = (e0 + 0 < n) ? r[e0 + 0] : 0.f;
                float x1 = (e0 + 1 < n) ? r[e0 + 1] : 0.f;
                float x2 = (e0 + 2 < n) ? r[e0 + 2] : 0.f;
                float x3 = (e0 + 3 < n) ? r[e0 + 3] : 0.f;

                s += (x0 + x1) + (x2 + x3);
                q = fmaf(x0, x0, q); q = fmaf(x1, x1, q);
                q = fmaf(x2, x2, q); q = fmaf(x3, x3, q);

                float rp0 = __shfl_up_sync(FULLMASK, x3, 1);
                if (lane == 0) rp0 = rlast;

                float c0, c1, c2, c3;
                { float t = rp0; float cf = (t < 0.f) ? ag : alpha; c0 = fmaf(cf * t, t, omega); }
                { float t = x0;  float cf = (t < 0.f) ? ag : alpha; c1 = fmaf(cf * t, t, omega); }
                { float t = x1;  float cf = (t < 0.f) ? ag : alpha; c2 = fmaf(cf * t, t, omega); }
                { float t = x2;  float cf = (t < 0.f) ? ag : alpha; c3 = fmaf(cf * t, t, omega); }

                float p0 = c0;
                float p1 = fmaf(bp1, p0, c1);
                float p2 = fmaf(bp1, p1, c2);
                float p3 = fmaf(bp1, p2, c3);

                float A = bp4, B = p3;
                #pragma unroll
                for (int d = 1; d < 32; d <<= 1) {
                    float Bp = __shfl_up_sync(FULLMASK, B, d);
                    float Ap = __shfl_up_sync(FULLMASK, A, d);
                    if (lane >= d) { B = fmaf(A, Bp, B); A *= Ap; }
                }
                float Bu = __shfl_up_sync(FULLMASK, B, 1);
                float Bx = (lane == 0) ? 0.f : Bu;
                float Hl = fmaf(bl4, Hc, Bx);

                float h0v = fmaf(bp1, Hl, p0);
                float h1v = fmaf(bp2, Hl, p1);
                float h2v = fmaf(b3,  Hl, p2);
                float h3v = fmaf(bp4, Hl, p3);

                if (e0 + 0 < n) { out[n + e0 + 0] = h0v; out[e0 + 0] = sqrt_approx(h0v); }
                if (e0 + 1 < n) { out[n + e0 + 1] = h1v; out[e0 + 1] = sqrt_approx(h1v); }
                if (e0 + 2 < n) { out[n + e0 + 2] = h2v; out[e0 + 2] = sqrt_approx(h2v); }
                if (e0 + 3 < n) { out[n + e0 + 3] = h3v; out[e0 + 3] = sqrt_approx(h3v); }

                Hc    = __shfl_sync(FULLMASK, h3v, 31);
                rlast = __shfl_sync(FULLMASK, x3, 31);
            }
        }
    }

    // ---- block reduction of variance partials ----
    #pragma unroll
    for (int d = 16; d; d >>= 1) {
        s += __shfl_xor_sync(FULLMASK, s, d);
        q += __shfl_xor_sync(FULLMASK, q, d);
    }
    __shared__ float rs[WPB], rq[WPB];
    __shared__ bool  sLast;
    if (lane == 0) { rs[w] = s; rq[w] = q; }
    __syncthreads();
    if (tid == 0) {
        float S = 0.f, Q = 0.f;
        #pragma unroll
        for (int i = 0; i < WPB; i++) { S += rs[i]; Q += rq[i]; }
        g_ps[blockIdx.x] = S;
        g_pq[blockIdx.x] = Q;
    }
    __threadfence();
    __syncthreads();
    if (tid == 0) {
        unsigned c = atomicAdd(&g_done, 1u);
        sLast = (c == gridDim.x - 1);
    }
    __syncthreads();

    // ---- last block: fold partials -> h0, fixup outputs [0,1024) ----
    if (sLast) {
        __threadfence();
        __shared__ double ss[TPB], sq2[TPB];
        __shared__ float  sh0;
        const int nb = gridDim.x;
        double ds = 0.0, dq = 0.0;
        for (int i = tid; i < nb; i += TPB) {
            ds += (double)g_ps[i];
            dq += (double)g_pq[i];
        }
        ss[tid] = ds; sq2[tid] = dq;
        __syncthreads();
        for (int ofs = TPB / 2; ofs; ofs >>= 1) {
            if (tid < ofs) { ss[tid] += ss[tid + ofs]; sq2[tid] += sq2[tid + ofs]; }
            __syncthreads();
        }
        if (tid == 0) {
            double S = ss[0], Q = sq2[0];
            sh0 = (float)((Q - S * S / (double)n) / (double)(n - 1));
            g_done = 0;                       // reset for next graph replay
        }
        __syncthreads();

        if (tid < 32) {                       // 1 warp recomputes [0, 1024)
            const float h0 = sh0;
            const int a = lane * 32;

            float h = 0.f;
            {
                float rp = (a > 0 && a - 1 < n) ? r[a - 1] : 0.f;
                #pragma unroll
                for (int k = 0; k < 32; k++) {
                    float rv = (a + k < n) ? r[a + k] : 0.f;
                    float c;
                    if (a + k == 0) c = h0;
                    else { float cf = (rp < 0.f) ? ag : alpha; c = fmaf(cf * rp, rp, omega); }
                    h  = fmaf(beta, h, c);
                    rp = rv;
                }
            }
            float A = bp32, B = h;
            #pragma unroll
            for (int d = 1; d < 32; d <<= 1) {
                float Bp = __shfl_up_sync(FULLMASK, B, d);
                float Ap = __shfl_up_sync(FULLMASK, A, d);
                if (lane >= d) { B = fmaf(A, Bp, B); A *= Ap; }
            }
            float Bprev = __shfl_up_sync(FULLMASK, B, 1);
            float Hin = (lane == 0) ? 0.f : Bprev;

            {
                float rp = (a > 0 && a - 1 < n) ? r[a - 1] : 0.f;
                h = Hin;
                #pragma unroll
                for (int k = 0; k < 32; k++) {
                    float rv = (a + k < n) ? r[a + k] : 0.f;
                    float c;
                    if (a + k == 0) c = h0;
                    else { float cf = (rp < 0.f) ? ag : alpha; c = fmaf(cf * rp, rp, omega); }
                    h = fmaf(beta, h, c);
                    if (a + k < n) {
                        out[n + a + k] = h;
                        out[a + k]     = sqrt_approx(h);
                    }
                    rp = rv;
                }
            }
        }
    }
}

// ---------------------------------------------------------------------------
extern "C" void kernel_launch(void* const* d_in, const int* in_sizes, int n_in,
                              void* d_out, int out_size)
{
    const float* r       = (const float*)d_in[0];
    const float* p_omega = (const float*)d_in[1];
    const float* p_alpha = (const float*)d_in[2];
    const float* p_beta  = (const float*)d_in[3];
    const float* p_gamma = (const float*)d_in[4];
    const int n = in_sizes[0];

    const int nb = (n + BLK - 1) / BLK;
    k_all<<<nb, TPB>>>(r, p_omega, p_alpha, p_beta, p_gamma, (float*)d_out, n);
}

// round 8
// speedup vs baseline: 1.0874x; 1.0874x over previous
#include <cuda_runtime.h>
#include <math.h>

// GJR-GARCH(1,1):  h[t] = c[t] + beta*h[t-1],  h[0]=var(returns,ddof=1)
// c[t] = omega + (alpha + gamma*[r[t-1]<0]) * r[t-1]^2
// Output: [sqrt(h) | h], each N floats.
//
// Warp owns 2048 elems = 16 rounds of 128 (lane owns a float4), 4-way ILP
// groups with SOFTWARE PREFETCH (group g+1 loads issued before group g
// compute). B-only warp scan with uniform step multipliers (beta^4)^d.
// 128-term window carry. TPB=128 -> grid 2048 blocks (tail-wave fix).
// Variance partials fused; last block folds h0 + fixes outputs [0,1024).
// (Resubmission of R7 — previous run hit a broker/container infra failure.)

#define WPB   4
#define TPB   (WPB * 32)        // 128
#define CHUNK 2048
#define BLK   (WPB * CHUNK)     // 8192 elements per block
#define NPART_MAX 32768
#define FULLMASK 0xffffffffu

__device__ float    g_ps[NPART_MAX];
__device__ float    g_pq[NPART_MAX];
__device__ unsigned g_done = 0;

__device__ __forceinline__ float sqrt_approx(float x) {
    float y; asm("sqrt.approx.f32 %0, %1;" : "=f"(y) : "f"(x)); return y;
}

// exact m^e for 0<=e<=31 from precomputed squarings
__device__ __forceinline__ float powk(float m1, float m2, float m4,
                                      float m8, float m16, int e) {
    float p = 1.f;
    if (e & 1)  p *= m1;
    if (e & 2)  p *= m2;
    if (e & 4)  p *= m4;
    if (e & 8)  p *= m8;
    if (e & 16) p *= m16;
    return p;
}

__global__ void __launch_bounds__(TPB) k_all(
    const float* __restrict__ r,
    const float* __restrict__ p_omega, const float* __restrict__ p_alpha,
    const float* __restrict__ p_beta,  const float* __restrict__ p_gamma,
    float* __restrict__ out, int n)
{
    const int tid  = threadIdx.x;
    const int w    = tid >> 5;
    const int lane = tid & 31;
    const int base = blockIdx.x * BLK + w * CHUNK;

    const float omega = __ldg(p_omega);
    const float alpha = __ldg(p_alpha);
    const float beta  = __ldg(p_beta);
    const float gamma = __ldg(p_gamma);
    const float ag = alpha + gamma;

    // powers of beta with power-of-two exponents (exact squarings)
    const float bp1 = beta;
    const float bp2 = bp1 * bp1, bp4 = bp2 * bp2, bp8 = bp4 * bp4;
    const float bp16 = bp8 * bp8, bp32 = bp16 * bp16;
    const float bp64 = bp32 * bp32, bp128 = bp64 * bp64;
    const float b3 = bp1 * bp2;

    // per-lane constant: beta^(4*lane)
    const float bl4 = powk(bp4, bp8, bp16, bp32, bp64, lane);

    float s = 0.f, q = 0.f;

    if (base < n) {
        // ---- chunk carry-in Hc ~= h[base-1]: 128-term window (coalesced) ----
        float Hc = 0.f;
        if (base > 0) {
            float bj = powk(bp1, bp2, bp4, bp8, bp16, lane);   // beta^lane
            float P  = 0.f;
            const float* rb = r + base - 2 - lane;       // term j = 32*i + lane
            #pragma unroll
            for (int i = 0; i < 4; i++) {
                float rp   = rb[-32 * i];
                float coef = (rp < 0.f) ? ag : alpha;
                P  = fmaf(bj, fmaf(coef * rp, rp, omega), P);
                bj *= bp32;
            }
            #pragma unroll
            for (int d = 16; d; d >>= 1) P += __shfl_xor_sync(FULLMASK, P, d);
            Hc = P;
        }
        float rlast = (base > 0) ? __ldg(r + base - 1) : 0.f;

        if (base + CHUNK <= n && ((n & 3) == 0)) {
            // ========= fast path: 4 groups x 4 ILP rounds, prefetched =========
            const float4* r4  = (const float4*)(r + base);
            float4*       oh4 = (float4*)(out + n + base);
            float4*       os4 = (float4*)(out + base);

            // prologue: load group 0
            float4 v[4];
            #pragma unroll
            for (int i = 0; i < 4; i++) v[i] = r4[i * 32 + lane];

            #pragma unroll
            for (int g = 0; g < 4; g++) {
                // prefetch group g+1 before computing group g
                float4 vn[4];
                if (g < 3) {
                    #pragma unroll
                    for (int i = 0; i < 4; i++)
                        vn[i] = r4[(4 * (g + 1) + i) * 32 + lane];
                }

                // c-transform + local affine prefix; variance fused
                float p0[4], p1[4], p2[4], p3[4];
                float rl_next = rlast;
                #pragma unroll
                for (int i = 0; i < 4; i++) {
                    s += (v[i].x + v[i].y) + (v[i].z + v[i].w);
                    q = fmaf(v[i].x, v[i].x, q); q = fmaf(v[i].y, v[i].y, q);
                    q = fmaf(v[i].z, v[i].z, q); q = fmaf(v[i].w, v[i].w, q);

                    float su  = __shfl_up_sync(FULLMASK, v[i].w, 1);
                    float t31 = __shfl_sync(FULLMASK, v[i].w, 31);
                    float rp0 = (lane == 0) ? rl_next : su;
                    rl_next = t31;

                    float c0, c1, c2, c3;
                    { float t = rp0;    float cf = (t < 0.f) ? ag : alpha; c0 = fmaf(cf * t, t, omega); }
                    { float t = v[i].x; float cf = (t < 0.f) ? ag : alpha; c1 = fmaf(cf * t, t, omega); }
                    { float t = v[i].y; float cf = (t < 0.f) ? ag : alpha; c2 = fmaf(cf * t, t, omega); }
                    { float t = v[i].z; float cf = (t < 0.f) ? ag : alpha; c3 = fmaf(cf * t, t, omega); }
                    p0[i] = c0;
                    p1[i] = fmaf(bp1, c0, c1);
                    p2[i] = fmaf(bp1, p1[i], c2);
                    p3[i] = fmaf(bp1, p2[i], c3);
                }
                rlast = rl_next;

                // 4 interleaved B-only warp scans; step d multiplier = (beta^4)^d
                float B[4];
                #pragma unroll
                for (int i = 0; i < 4; i++) B[i] = p3[i];
                {
                    float Bp[4];
                    #pragma unroll
                    for (int i = 0; i < 4; i++) Bp[i] = __shfl_up_sync(FULLMASK, B[i], 1);
                    #pragma unroll
                    for (int i = 0; i < 4; i++) if (lane >= 1) B[i] = fmaf(bp4, Bp[i], B[i]);
                    #pragma unroll
                    for (int i = 0; i < 4; i++) Bp[i] = __shfl_up_sync(FULLMASK, B[i], 2);
                    #pragma unroll
                    for (int i = 0; i < 4; i++) if (lane >= 2) B[i] = fmaf(bp8, Bp[i], B[i]);
                    #pragma unroll
                    for (int i = 0; i < 4; i++) Bp[i] = __shfl_up_sync(FULLMASK, B[i], 4);
                    #pragma unroll
                    for (int i = 0; i < 4; i++) if (lane >= 4) B[i] = fmaf(bp16, Bp[i], B[i]);
                    #pragma unroll
                    for (int i = 0; i < 4; i++) Bp[i] = __shfl_up_sync(FULLMASK, B[i], 8);
                    #pragma unroll
                    for (int i = 0; i < 4; i++) if (lane >= 8) B[i] = fmaf(bp32, Bp[i], B[i]);
                    #pragma unroll
                    for (int i = 0; i < 4; i++) Bp[i] = __shfl_up_sync(FULLMASK, B[i], 16);
                    #pragma unroll
                    for (int i = 0; i < 4; i++) if (lane >= 16) B[i] = fmaf(bp64, Bp[i], B[i]);
                }

                // exclusive value + totals, carry chain (one fma per round)
                float Bx[4], T[4];
                #pragma unroll
                for (int i = 0; i < 4; i++) {
                    float bu = __shfl_up_sync(FULLMASK, B[i], 1);
                    Bx[i] = (lane == 0) ? 0.f : bu;
                    T[i]  = __shfl_sync(FULLMASK, B[i], 31);
                }
                float Hin[4];
                Hin[0] = Hc;
                Hin[1] = fmaf(bp128, Hin[0], T[0]);
                Hin[2] = fmaf(bp128, Hin[1], T[1]);
                Hin[3] = fmaf(bp128, Hin[2], T[2]);
                Hc     = fmaf(bp128, Hin[3], T[3]);

                // apply carries + streaming stores
                #pragma unroll
                for (int i = 0; i < 4; i++) {
                    float Hl = fmaf(bl4, Hin[i], Bx[i]);   // h[a-1] for this lane
                    float h0v = fmaf(bp1, Hl, p0[i]);
                    float h1v = fmaf(bp2, Hl, p1[i]);
                    float h2v = fmaf(b3,  Hl, p2[i]);
                    float h3v = fmaf(bp4, Hl, p3[i]);
                    __stcs(&oh4[(4 * g + i) * 32 + lane],
                           make_float4(h0v, h1v, h2v, h3v));
                    __stcs(&os4[(4 * g + i) * 32 + lane],
                           make_float4(sqrt_approx(h0v), sqrt_approx(h1v),
                                       sqrt_approx(h2v), sqrt_approx(h3v)));
                }

                // rotate pipeline
                #pragma unroll
                for (int i = 0; i < 4; i++) v[i] = vn[i];
            }
        } else {
            // =============== guarded scalar path (partial chunk) ===============
            #pragma unroll 1
            for (int j = 0; j < CHUNK / 128; j++) {
                int e0 = base + j * 128 + 4 * lane;
                float x0 = (e0 + 0 < n) ? r[e0 + 0] : 0.f;
                float x1 = (e0 + 1 < n) ? r[e0 + 1] : 0.f;
                float x2 = (e0 + 2 < n) ? r[e0 + 2] : 0.f;
                float x3 = (e0 + 3 < n) ? r[e0 + 3] : 0.f;

                s += (x0 + x1) + (x2 + x3);
                q = fmaf(x0, x0, q); q = fmaf(x1, x1, q);
                q = fmaf(x2, x2, q); q = fmaf(x3, x3, q);

                float rp0 = __shfl_up_sync(FULLMASK, x3, 1);
                if (lane == 0) rp0 = rlast;

                float c0, c1, c2, c3;
                { float t = rp0; float cf = (t < 0.f) ? ag : alpha; c0 = fmaf(cf * t, t, omega); }
                { float t = x0;  float cf = (t < 0.f) ? ag : alpha; c1 = fmaf(cf * t, t, omega); }
                { float t = x1;  float cf = (t < 0.f) ? ag : alpha; c2 = fmaf(cf * t, t, omega); }
                { float t = x2;  float cf = (t < 0.f) ? ag : alpha; c3 = fmaf(cf * t, t, omega); }

                float p0 = c0;
                float p1 = fmaf(bp1, p0, c1);
                float p2 = fmaf(bp1, p1, c2);
                float p3 = fmaf(bp1, p2, c3);

                float A = bp4, B = p3;
                #pragma unroll
                for (int d = 1; d < 32; d <<= 1) {
                    float Bp = __shfl_up_sync(FULLMASK, B, d);
                    float Ap = __shfl_up_sync(FULLMASK, A, d);
                    if (lane >= d) { B = fmaf(A, Bp, B); A *= Ap; }
                }
                float Bu = __shfl_up_sync(FULLMASK, B, 1);
                float Bx = (lane == 0) ? 0.f : Bu;
                float Hl = fmaf(bl4, Hc, Bx);

                float h0v = fmaf(bp1, Hl, p0);
                float h1v = fmaf(bp2, Hl, p1);
                float h2v = fmaf(b3,  Hl, p2);
                float h3v = fmaf(bp4, Hl, p3);

                if (e0 + 0 < n) { out[n + e0 + 0] = h0v; out[e0 + 0] = sqrt_approx(h0v); }
                if (e0 + 1 < n) { out[n + e0 + 1] = h1v; out[e0 + 1] = sqrt_approx(h1v); }
                if (e0 + 2 < n) { out[n + e0 + 2] = h2v; out[e0 + 2] = sqrt_approx(h2v); }
                if (e0 + 3 < n) { out[n + e0 + 3] = h3v; out[e0 + 3] = sqrt_approx(h3v); }

                Hc    = __shfl_sync(FULLMASK, h3v, 31);
                rlast = __shfl_sync(FULLMASK, x3, 31);
            }
        }
    }

    // ---- block reduction of variance partials ----
    #pragma unroll
    for (int d = 16; d; d >>= 1) {
        s += __shfl_xor_sync(FULLMASK, s, d);
        q += __shfl_xor_sync(FULLMASK, q, d);
    }
    __shared__ float rs[WPB], rq[WPB];
    __shared__ bool  sLast;
    if (lane == 0) { rs[w] = s; rq[w] = q; }
    __syncthreads();
    if (tid == 0) {
        float S = 0.f, Q = 0.f;
        #pragma unroll
        for (int i = 0; i < WPB; i++) { S += rs[i]; Q += rq[i]; }
        g_ps[blockIdx.x] = S;
        g_pq[blockIdx.x] = Q;
    }
    __threadfence();
    __syncthreads();
    if (tid == 0) {
        unsigned c = atomicAdd(&g_done, 1u);
        sLast = (c == gridDim.x - 1);
    }
    __syncthreads();

    // ---- last block: fold partials -> h0, fixup outputs [0,1024) ----
    if (sLast) {
        __threadfence();
        __shared__ double ss[TPB], sq2[TPB];
        __shared__ float  sh0;
        const int nb = gridDim.x;
        double ds = 0.0, dq = 0.0;
        for (int i = tid; i < nb; i += TPB) {
            ds += (double)g_ps[i];
            dq += (double)g_pq[i];
        }
        ss[tid] = ds; sq2[tid] = dq;
        __syncthreads();
        for (int ofs = TPB / 2; ofs; ofs >>= 1) {
            if (tid < ofs) { ss[tid] += ss[tid + ofs]; sq2[tid] += sq2[tid + ofs]; }
            __syncthreads();
        }
        if (tid == 0) {
            double S = ss[0], Q = sq2[0];
            sh0 = (float)((Q - S * S / (double)n) / (double)(n - 1));
            g_done = 0;                       // reset for next graph replay
        }
        __syncthreads();

        if (tid < 32) {                       // 1 warp recomputes [0, 1024)
            const float h0 = sh0;
            const int a = lane * 32;

            float h = 0.f;
            {
                float rp = (a > 0 && a - 1 < n) ? r[a - 1] : 0.f;
                #pragma unroll
                for (int k = 0; k < 32; k++) {
                    float rv = (a + k < n) ? r[a + k] : 0.f;
                    float c;
                    if (a + k == 0) c = h0;
                    else { float cf = (rp < 0.f) ? ag : alpha; c = fmaf(cf * rp, rp, omega); }
                    h  = fmaf(beta, h, c);
                    rp = rv;
                }
            }
            float A = bp32, B = h;
            #pragma unroll
            for (int d = 1; d < 32; d <<= 1) {
                float Bp = __shfl_up_sync(FULLMASK, B, d);
                float Ap = __shfl_up_sync(FULLMASK, A, d);
                if (lane >= d) { B = fmaf(A, Bp, B); A *= Ap; }
            }
            float Bprev = __shfl_up_sync(FULLMASK, B, 1);
            float Hin = (lane == 0) ? 0.f : Bprev;

            {
                float rp = (a > 0 && a - 1 < n) ? r[a - 1] : 0.f;
                h = Hin;
                #pragma unroll
                for (int k = 0; k < 32; k++) {
                    float rv = (a + k < n) ? r[a + k] : 0.f;
                    float c;
                    if (a + k == 0) c = h0;
                    else { float cf = (rp < 0.f) ? ag : alpha; c = fmaf(cf * rp, rp, omega); }
                    h = fmaf(beta, h, c);
                    if (a + k < n) {
                        out[n + a + k] = h;
                        out[a + k]     = sqrt_approx(h);
                    }
                    rp = rv;
                }
            }
        }
    }
}

// ---------------------------------------------------------------------------
extern "C" void kernel_launch(void* const* d_in, const int* in_sizes, int n_in,
                              void* d_out, int out_size)
{
    const float* r       = (const float*)d_in[0];
    const float* p_omega = (const float*)d_in[1];
    const float* p_alpha = (const float*)d_in[2];
    const float* p_beta  = (const float*)d_in[3];
    const float* p_gamma = (const float*)d_in[4];
    const int n = in_sizes[0];

    const int nb = (n + BLK - 1) / BLK;
    k_all<<<nb, TPB>>>(r, p_omega, p_alpha, p_beta, p_gamma, (float*)d_out, n);
}

// round 10
// speedup vs baseline: 1.1198x; 1.0298x over previous
#include <cuda_runtime.h>
#include <cstdint>
#include <math.h>

// GJR-GARCH(1,1):  h[t] = c[t] + beta*h[t-1],  h[0]=var(returns,ddof=1)
// c[t] = omega + (alpha + gamma*[r[t-1]<0]) * r[t-1]^2
// Output: [sqrt(h) | h], each N floats.
//
// R9b: cp.async double-buffered SMEM staging (MLP without register cost).
// Warp owns 2048 elems = 4 groups of 512 (4 rounds of 128; lane owns float4).
// Per-warp async pipeline: stage g+2 while computing g. B-only warp scan with
// uniform step multipliers (beta^4)^d. 128-term window carry. TPB=128.
// Variance fused; last block folds h0 + fixes outputs [0,1024).
// (R9 failed to compile: missing <cstdint> for uint32_t. Logic unchanged.)

#define WPB    4
#define TPB    (WPB * 32)        // 128
#define CHUNK  2048
#define BLK    (WPB * CHUNK)     // 8192 elements per block
#define GRP    512               // elements per staged group
#define NG     (CHUNK / GRP)     // 4 groups
#define NPART_MAX 32768
#define FULLMASK 0xffffffffu

__device__ float    g_ps[NPART_MAX];
__device__ float    g_pq[NPART_MAX];
__device__ unsigned g_done = 0;

__device__ __forceinline__ float sqrt_approx(float x) {
    float y; asm("sqrt.approx.f32 %0, %1;" : "=f"(y) : "f"(x)); return y;
}

__device__ __forceinline__ void cp_async16(unsigned saddr, const void* gptr) {
    asm volatile("cp.async.cg.shared.global [%0], [%1], 16;"
                 :: "r"(saddr), "l"(gptr));
}
__device__ __forceinline__ void cp_commit() {
    asm volatile("cp.async.commit_group;");
}

// exact m^e for 0<=e<=31 from precomputed squarings
__device__ __forceinline__ float powk(float m1, float m2, float m4,
                                      float m8, float m16, int e) {
    float p = 1.f;
    if (e & 1)  p *= m1;
    if (e & 2)  p *= m2;
    if (e & 4)  p *= m4;
    if (e & 8)  p *= m8;
    if (e & 16) p *= m16;
    return p;
}

__global__ void __launch_bounds__(TPB) k_all(
    const float* __restrict__ r,
    const float* __restrict__ p_omega, const float* __restrict__ p_alpha,
    const float* __restrict__ p_beta,  const float* __restrict__ p_gamma,
    float* __restrict__ out, int n)
{
    __shared__ alignas(16) float stage[WPB][2][GRP];   // 16 KB staging ring

    const int tid  = threadIdx.x;
    const int w    = tid >> 5;
    const int lane = tid & 31;
    const int base = blockIdx.x * BLK + w * CHUNK;

    const float omega = __ldg(p_omega);
    const float alpha = __ldg(p_alpha);
    const float beta  = __ldg(p_beta);
    const float gamma = __ldg(p_gamma);
    const float ag = alpha + gamma;

    // powers of beta with power-of-two exponents (exact squarings)
    const float bp1 = beta;
    const float bp2 = bp1 * bp1, bp4 = bp2 * bp2, bp8 = bp4 * bp4;
    const float bp16 = bp8 * bp8, bp32 = bp16 * bp16;
    const float bp64 = bp32 * bp32, bp128 = bp64 * bp64;
    const float b3 = bp1 * bp2;

    // per-lane constant: beta^(4*lane)
    const float bl4 = powk(bp4, bp8, bp16, bp32, bp64, lane);

    float s = 0.f, q = 0.f;

    if (base < n) {
        // ---- chunk carry-in Hc ~= h[base-1]: 128-term window (coalesced) ----
        float Hc = 0.f;
        if (base > 0) {
            float bj = powk(bp1, bp2, bp4, bp8, bp16, lane);   // beta^lane
            float P  = 0.f;
            const float* rb = r + base - 2 - lane;       // term j = 32*i + lane
            #pragma unroll
            for (int i = 0; i < 4; i++) {
                float rp   = rb[-32 * i];
                float coef = (rp < 0.f) ? ag : alpha;
                P  = fmaf(bj, fmaf(coef * rp, rp, omega), P);
                bj *= bp32;
            }
            #pragma unroll
            for (int d = 16; d; d >>= 1) P += __shfl_xor_sync(FULLMASK, P, d);
            Hc = P;
        }
        float rlast = (base > 0) ? __ldg(r + base - 1) : 0.f;

        if (base + CHUNK <= n && ((n & 3) == 0)) {
            // ======== fast path: cp.async double-buffered group pipeline ========
            float4* oh4 = (float4*)(out + n + base);
            float4* os4 = (float4*)(out + base);

            // prologue: stage groups 0 and 1
            #pragma unroll
            for (int g = 0; g < 2; g++) {
                #pragma unroll
                for (int i = 0; i < 4; i++) {
                    int e = i * 128 + 4 * lane;
                    unsigned sa = (unsigned)__cvta_generic_to_shared(
                        &stage[w][g][e]);
                    cp_async16(sa, r + base + g * GRP + e);
                }
                cp_commit();
            }

            #pragma unroll
            for (int g = 0; g < NG; g++) {
                const int buf = g & 1;
                // wait for stage g (allow next group still in flight)
                if (g < NG - 1) asm volatile("cp.async.wait_group 1;");
                else            asm volatile("cp.async.wait_group 0;");
                __syncwarp();

                const float* sg = stage[w][buf];

                // load 4 rounds' float4s from SMEM (conflict-free LDS.128)
                float4 v[4];
                #pragma unroll
                for (int i = 0; i < 4; i++)
                    v[i] = *(const float4*)&sg[i * 128 + 4 * lane];
                float rl_next = sg[GRP - 1];   // broadcast LDS, for next group

                // c-transform + local affine prefix; variance fused
                float p0[4], p1[4], p2[4], p3[4];
                #pragma unroll
                for (int i = 0; i < 4; i++) {
                    s += (v[i].x + v[i].y) + (v[i].z + v[i].w);
                    q = fmaf(v[i].x, v[i].x, q); q = fmaf(v[i].y, v[i].y, q);
                    q = fmaf(v[i].z, v[i].z, q); q = fmaf(v[i].w, v[i].w, q);

                    float su  = __shfl_up_sync(FULLMASK, v[i].w, 1);
                    float rp0 = su;
                    if (lane == 0)
                        rp0 = (i == 0) ? rlast : sg[i * 128 - 1];

                    float c0, c1, c2, c3;
                    { float t = rp0;    float cf = (t < 0.f) ? ag : alpha; c0 = fmaf(cf * t, t, omega); }
                    { float t = v[i].x; float cf = (t < 0.f) ? ag : alpha; c1 = fmaf(cf * t, t, omega); }
                    { float t = v[i].y; float cf = (t < 0.f) ? ag : alpha; c2 = fmaf(cf * t, t, omega); }
                    { float t = v[i].z; float cf = (t < 0.f) ? ag : alpha; c3 = fmaf(cf * t, t, omega); }
                    p0[i] = c0;
                    p1[i] = fmaf(bp1, c0, c1);
                    p2[i] = fmaf(bp1, p1[i], c2);
                    p3[i] = fmaf(bp1, p2[i], c3);
                }
                rlast = rl_next;

                // done reading this buffer; refill it with group g+2
                __syncwarp();
                if (g + 2 < NG) {
                    #pragma unroll
                    for (int i = 0; i < 4; i++) {
                        int e = i * 128 + 4 * lane;
                        unsigned sa = (unsigned)__cvta_generic_to_shared(
                            &stage[w][buf][e]);
                        cp_async16(sa, r + base + (g + 2) * GRP + e);
                    }
                    cp_commit();
                }

                // 4 interleaved B-only warp scans; step d multiplier = (beta^4)^d
                float B[4];
                #pragma unroll
                for (int i = 0; i < 4; i++) B[i] = p3[i];
                {
                    float Bp[4];
                    #pragma unroll
                    for (int i = 0; i < 4; i++) Bp[i] = __shfl_up_sync(FULLMASK, B[i], 1);
                    #pragma unroll
                    for (int i = 0; i < 4; i++) if (lane >= 1) B[i] = fmaf(bp4, Bp[i], B[i]);
                    #pragma unroll
                    for (int i = 0; i < 4; i++) Bp[i] = __shfl_up_sync(FULLMASK, B[i], 2);
                    #pragma unroll
                    for (int i = 0; i < 4; i++) if (lane >= 2) B[i] = fmaf(bp8, Bp[i], B[i]);
                    #pragma unroll
                    for (int i = 0; i < 4; i++) Bp[i] = __shfl_up_sync(FULLMASK, B[i], 4);
                    #pragma unroll
                    for (int i = 0; i < 4; i++) if (lane >= 4) B[i] = fmaf(bp16, Bp[i], B[i]);
                    #pragma unroll
                    for (int i = 0; i < 4; i++) Bp[i] = __shfl_up_sync(FULLMASK, B[i], 8);
                    #pragma unroll
                    for (int i = 0; i < 4; i++) if (lane >= 8) B[i] = fmaf(bp32, Bp[i], B[i]);
                    #pragma unroll
                    for (int i = 0; i < 4; i++) Bp[i] = __shfl_up_sync(FULLMASK, B[i], 16);
                    #pragma unroll
                    for (int i = 0; i < 4; i++) if (lane >= 16) B[i] = fmaf(bp64, Bp[i], B[i]);
                }

                // exclusive value + totals, carry chain (one fma per round)
                float Bx[4], T[4];
                #pragma unroll
                for (int i = 0; i < 4; i++) {
                    float bu = __shfl_up_sync(FULLMASK, B[i], 1);
                    Bx[i] = (lane == 0) ? 0.f : bu;
                    T[i]  = __shfl_sync(FULLMASK, B[i], 31);
                }
                float Hin[4];
                Hin[0] = Hc;
                Hin[1] = fmaf(bp128, Hin[0], T[0]);
                Hin[2] = fmaf(bp128, Hin[1], T[1]);
                Hin[3] = fmaf(bp128, Hin[2], T[2]);
                Hc     = fmaf(bp128, Hin[3], T[3]);

                // apply carries + streaming stores
                #pragma unroll
                for (int i = 0; i < 4; i++) {
                    float Hl = fmaf(bl4, Hin[i], Bx[i]);   // h[a-1] for this lane
                    float h0v = fmaf(bp1, Hl, p0[i]);
                    float h1v = fmaf(bp2, Hl, p1[i]);
                    float h2v = fmaf(b3,  Hl, p2[i]);
                    float h3v = fmaf(bp4, Hl, p3[i]);
                    int idx = (g * 4 + i) * 32 + lane;
                    __stcs(&oh4[idx], make_float4(h0v, h1v, h2v, h3v));
                    __stcs(&os4[idx],
                           make_float4(sqrt_approx(h0v), sqrt_approx(h1v),
                                       sqrt_approx(h2v), sqrt_approx(h3v)));
                }
            }
        } else {
            // =============== guarded scalar path (partial chunk) ===============
            #pragma unroll 1
            for (int j = 0; j < CHUNK / 128; j++) {
                int e0 = base + j * 128 + 4 * lane;
                float x0 = (e0 + 0 < n) ? r[e0 + 0] : 0.f;
                float x1 = (e0 + 1 < n) ? r[e0 + 1] : 0.f;
                float x2 = (e0 + 2 < n) ? r[e0 + 2] : 0.f;
                float x3 = (e0 + 3 < n) ? r[e0 + 3] : 0.f;

                s += (x0 + x1) + (x2 + x3);
                q = fmaf(x0, x0, q); q = fmaf(x1, x1, q);
                q = fmaf(x2, x2, q); q = fmaf(x3, x3, q);

                float rp0 = __shfl_up_sync(FULLMASK, x3, 1);
                if (lane == 0) rp0 = rlast;

                float c0, c1, c2, c3;
                { float t = rp0; float cf = (t < 0.f) ? ag : alpha; c0 = fmaf(cf * t, t, omega); }
                { float t = x0;  float cf = (t < 0.f) ? ag : alpha; c1 = fmaf(cf * t, t, omega); }
                { float t = x1;  float cf = (t < 0.f) ? ag : alpha; c2 = fmaf(cf * t, t, omega); }
                { float t = x2;  float cf = (t < 0.f) ? ag : alpha; c3 = fmaf(cf * t, t, omega); }

                float p0 = c0;
                float p1 = fmaf(bp1, p0, c1);
                float p2 = fmaf(bp1, p1, c2);
                float p3 = fmaf(bp1, p2, c3);

                float A = bp4, B = p3;
                #pragma unroll
                for (int d = 1; d < 32; d <<= 1) {
                    float Bp = __shfl_up_sync(FULLMASK, B, d);
                    float Ap = __shfl_up_sync(FULLMASK, A, d);
                    if (lane >= d) { B = fmaf(A, Bp, B); A *= Ap; }
                }
                float Bu = __shfl_up_sync(FULLMASK, B, 1);
                float Bx = (lane == 0) ? 0.f : Bu;
                float Hl = fmaf(bl4, Hc, Bx);

                float h0v = fmaf(bp1, Hl, p0);
                float h1v = fmaf(bp2, Hl, p1);
                float h2v = fmaf(b3,  Hl, p2);
                float h3v = fmaf(bp4, Hl, p3);

                if (e0 + 0 < n) { out[n + e0 + 0] = h0v; out[e0 + 0] = sqrt_approx(h0v); }
                if (e0 + 1 < n) { out[n + e0 + 1] = h1v; out[e0 + 1] = sqrt_approx(h1v); }
                if (e0 + 2 < n) { out[n + e0 + 2] = h2v; out[e0 + 2] = sqrt_approx(h2v); }
                if (e0 + 3 < n) { out[n + e0 + 3] = h3v; out[e0 + 3] = sqrt_approx(h3v); }

                Hc    = __shfl_sync(FULLMASK, h3v, 31);
                rlast = __shfl_sync(FULLMASK, x3, 31);
            }
        }
    }

    // ---- block reduction of variance partials ----
    #pragma unroll
    for (int d = 16; d; d >>= 1) {
        s += __shfl_xor_sync(FULLMASK, s, d);
        q += __shfl_xor_sync(FULLMASK, q, d);
    }
    __shared__ float rs[WPB], rq[WPB];
    __shared__ bool  sLast;
    if (lane == 0) { rs[w] = s; rq[w] = q; }
    __syncthreads();
    if (tid == 0) {
        float S = 0.f, Q = 0.f;
        #pragma unroll
        for (int i = 0; i < WPB; i++) { S += rs[i]; Q += rq[i]; }
        g_ps[blockIdx.x] = S;
        g_pq[blockIdx.x] = Q;
    }
    __threadfence();
    __syncthreads();
    if (tid == 0) {
        unsigned c = atomicAdd(&g_done, 1u);
        sLast = (c == gridDim.x - 1);
    }
    __syncthreads();

    // ---- last block: fold partials -> h0, fixup outputs [0,1024) ----
    if (sLast) {
        __threadfence();
        __shared__ double ss[TPB], sq2[TPB];
        __shared__ float  sh0;
        const int nb = gridDim.x;
        double ds = 0.0, dq = 0.0;
        for (int i = tid; i < nb; i += TPB) {
            ds += (double)g_ps[i];
            dq += (double)g_pq[i];
        }
        ss[tid] = ds; sq2[tid] = dq;
        __syncthreads();
        for (int ofs = TPB / 2; ofs; ofs >>= 1) {
            if (tid < ofs) { ss[tid] += ss[tid + ofs]; sq2[tid] += sq2[tid + ofs]; }
            __syncthreads();
        }
        if (tid == 0) {
            double S = ss[0], Q = sq2[0];
            sh0 = (float)((Q - S * S / (double)n) / (double)(n - 1));
            g_done = 0;                       // reset for next graph replay
        }
        __syncthreads();

        if (tid < 32) {                       // 1 warp recomputes [0, 1024)
            const float h0 = sh0;
            const int a = lane * 32;

            float h = 0.f;
            {
                float rp = (a > 0 && a - 1 < n) ? r[a - 1] : 0.f;
                #pragma unroll
                for (int k = 0; k < 32; k++) {
                    float rv = (a + k < n) ? r[a + k] : 0.f;
                    float c;
                    if (a + k == 0) c = h0;
                    else { float cf = (rp < 0.f) ? ag : alpha; c = fmaf(cf * rp, rp, omega); }
                    h  = fmaf(beta, h, c);
                    rp = rv;
                }
            }
            float A = bp32, B = h;
            #pragma unroll
            for (int d = 1; d < 32; d <<= 1) {
                float Bp = __shfl_up_sync(FULLMASK, B, d);
                float Ap = __shfl_up_sync(FULLMASK, A, d);
                if (lane >= d) { B = fmaf(A, Bp, B); A *= Ap; }
            }
            float Bprev = __shfl_up_sync(FULLMASK, B, 1);
            float Hin = (lane == 0) ? 0.f : Bprev;

            {
                float rp = (a > 0 && a - 1 < n) ? r[a - 1] : 0.f;
                h = Hin;
                #pragma unroll
                for (int k = 0; k < 32; k++) {
                    float rv = (a + k < n) ? r[a + k] : 0.f;
                    float c;
                    if (a + k == 0) c = h0;
                    else { float cf = (rp < 0.f) ? ag : alpha; c = fmaf(cf * rp, rp, omega); }
                    h = fmaf(beta, h, c);
                    if (a + k < n) {
                        out[n + a + k] = h;
                        out[a + k]     = sqrt_approx(h);
                    }
                    rp = rv;
                }
            }
        }
    }
}

// ---------------------------------------------------------------------------
extern "C" void kernel_launch(void* const* d_in, const int* in_sizes, int n_in,
                              void* d_out, int out_size)
{
    const float* r       = (const float*)d_in[0];
    const float* p_omega = (const float*)d_in[1];
    const float* p_alpha = (const float*)d_in[2];
    const float* p_beta  = (const float*)d_in[3];
    const float* p_gamma = (const float*)d_in[4];
    const int n = in_sizes[0];

    const int nb = (n + BLK - 1) / BLK;
    k_all<<<nb, TPB>>>(r, p_omega, p_alpha, p_beta, p_gamma, (float*)d_out, n);
}